// round 13
// baseline (speedup 1.0000x reference)
#include <cuda_runtime.h>
#include <cuda_fp16.h>
#include <cstdint>

// Problem constants
#define BATCH 4
#define SEQ   2048
#define DIM   1024
#define SCALE 0.03125f   // 1024^-0.5

// GEMM tile config (fp16 mma.sync m16n8k16, cp.async multistage)
#define BM 256                             // CTA rows
#define BN 128                             // CTA cols
#define BK 128                             // halfs per k-chunk (256B rows)
#define KSN (BK / 16)                      // 8 k16-steps per chunk
#define STAGES 2
#define NTHREADS 256
#define ROWB 272                           // [*,K] row bytes (256 data + 16 pad); 68w % 32 = 4 -> conflict-free
#define ROWVB 272                          // [K,N] row bytes (256 data + 16 pad)
#define A_BYTES (BM * ROWB)                // 69632
#define BN_BYTES (BN * ROWB)               // 34816 (non-trans B tile)
#define BT_BYTES (BK * ROWVB)              // 34816 (trans B tile)

// Scratch (device globals: allocation-free rule)
static __device__ __half g_xh[BATCH * SEQ * DIM];
static __device__ __half g_wh[3 * DIM * DIM];
static __device__ __half g_qh[BATCH * SEQ * DIM];
static __device__ __half g_kh[BATCH * SEQ * DIM];
static __device__ __half g_vh[BATCH * SEQ * DIM];
static __device__ float  g_s[(size_t)BATCH * SEQ * SEQ];
static __device__ __half g_ph[(size_t)BATCH * SEQ * SEQ];

// ---------------------------------------------------------------------------
// helpers
// ---------------------------------------------------------------------------
static __device__ __forceinline__ uint32_t smem_u32(const void* p) {
    uint32_t a;
    asm("{ .reg .u64 t; cvta.to.shared.u64 t, %1; cvt.u32.u64 %0, t; }" : "=r"(a) : "l"(p));
    return a;
}

static __device__ __forceinline__ void ldsm_x4(uint32_t* r, uint32_t addr) {
    asm volatile("ldmatrix.sync.aligned.m8n8.x4.shared.b16 {%0,%1,%2,%3}, [%4];"
                 : "=r"(r[0]), "=r"(r[1]), "=r"(r[2]), "=r"(r[3]) : "r"(addr));
}
static __device__ __forceinline__ void ldsm_x4_t(uint32_t* r, uint32_t addr) {
    asm volatile("ldmatrix.sync.aligned.m8n8.x4.trans.shared.b16 {%0,%1,%2,%3}, [%4];"
                 : "=r"(r[0]), "=r"(r[1]), "=r"(r[2]), "=r"(r[3]) : "r"(addr));
}

static __device__ __forceinline__ void mma_f16(float* c, const uint32_t* a, const uint32_t* b) {
    asm volatile(
        "mma.sync.aligned.m16n8k16.row.col.f32.f16.f16.f32 "
        "{%0,%1,%2,%3}, {%4,%5,%6,%7}, {%8,%9}, {%0,%1,%2,%3};\n"
        : "+f"(c[0]), "+f"(c[1]), "+f"(c[2]), "+f"(c[3])
        : "r"(a[0]), "r"(a[1]), "r"(a[2]), "r"(a[3]),
          "r"(b[0]), "r"(b[1]));
}

static __device__ __forceinline__ void cp16(uint32_t dst, const void* src) {
    asm volatile("cp.async.ca.shared.global [%0], [%1], 16;" :: "r"(dst), "l"(src) : "memory");
}
static __device__ __forceinline__ void cp_commit() {
    asm volatile("cp.async.commit_group;" ::: "memory");
}
template <int N>
static __device__ __forceinline__ void cp_wait() {
    asm volatile("cp.async.wait_group %0;" :: "n"(N) : "memory");
}

// ---------------------------------------------------------------------------
// TN/NN GEMM (fp16 mma.sync m16n8k16, 2-stage cp.async, frag double-buffer):
//   TRANSB=false: C[m,n] = alpha * sum_k A[m,k] * B[n,k]   (B: [N,K], ldb)
//   TRANSB=true : C[m,n] = alpha * sum_k A[m,k] * B[k,n]   (B: [K,N], ldb)
// A: [M,K] half, K-contiguous. fp32 accumulation. Klim % BK == 0.
// 256x128 CTA tile, 8 warps (4x2), warp tile 64x64; BK=128 -> 8 k16-steps/iter.
// ---------------------------------------------------------------------------
template <typename OutT, bool TRANSB>
static __device__ __forceinline__ void gemm_h(
    const __half* __restrict__ A, int lda,
    const __half* __restrict__ B, int ldb,
    OutT* __restrict__ C, int ldc,
    int Klim, float alpha, int bm, int bn)
{
    constexpr uint32_t B_BYTES = TRANSB ? BT_BYTES : BN_BYTES;
    constexpr uint32_t STAGE_BYTES = A_BYTES + B_BYTES;

    extern __shared__ char smem[];
    const uint32_t sbase = smem_u32(smem);

    const int tid  = threadIdx.x;
    const int warp = tid >> 5;
    const int lane = tid & 31;
    const int wr = warp >> 1;          // 0..3: warp row (64-row band of 256)
    const int wc = warp & 1;           // 0..1: warp col (64-col band of 128)
    const int g  = lane >> 2;
    const int t  = lane & 3;

    // Staging maps (256B data rows, 16 segments of 16B):
    const int srow = tid >> 4;         // 0..15
    const int sseg = tid & 15;         // 0..15
    // A: rows srow+{0,16,...,240}: 16 cp16/thread.
    const __half* Abase = A + (long)(bm * BM + srow) * lda + sseg * 8;
    const uint32_t soffA = (uint32_t)srow * ROWB + (uint32_t)sseg * 16;
    // B: rows srow+{0,16,...,112}: 8 cp16/thread (both layouts have 128 rows).
    const __half* Bbase;
    if constexpr (!TRANSB) {
        Bbase = B + (long)(bn * BN + srow) * ldb + sseg * 8;
    } else {
        Bbase = B + (long)srow * ldb + bn * BN + sseg * 8;
    }
    const uint32_t soffB = (uint32_t)srow * ROWB + (uint32_t)sseg * 16;

    // ldmatrix per-lane byte offsets (within a stage buffer).
    const uint32_t aoff = (uint32_t)(wr * 64 + (lane & 15)) * ROWB + (uint32_t)(lane >> 4) * 16;
    uint32_t boff;
    if constexpr (!TRANSB) {
        boff = A_BYTES
            + (uint32_t)(wc * 64 + (lane & 7) + ((lane & 16) ? 8 : 0)) * ROWB
            + (uint32_t)((lane >> 3) & 1) * 16;
    } else {
        // trans: lanes 0-15 -> k=lane&15, n-col +0; lanes 16-31 -> n-col +8.
        boff = A_BYTES
            + (uint32_t)(lane & 15) * ROWVB
            + (uint32_t)(wc * 64 + ((lane >> 4) ? 8 : 0)) * 2;
    }

    float acc[4][8][4];
#pragma unroll
    for (int i = 0; i < 4; i++)
#pragma unroll
        for (int j = 0; j < 8; j++)
#pragma unroll
            for (int r = 0; r < 4; r++) acc[i][j][r] = 0.0f;

    const int n = Klim / BK;

#define ISSUE_STAGE(stage, itv)                                                 \
    do {                                                                        \
        if ((itv) < n) {                                                        \
            const uint32_t sa = sbase + (uint32_t)(stage) * STAGE_BYTES + soffA;\
            const uint32_t sb = sbase + (uint32_t)(stage) * STAGE_BYTES         \
                              + A_BYTES + soffB;                                \
            const __half* ag = Abase + (long)(itv) * BK;                        \
            _Pragma("unroll")                                                   \
            for (int p = 0; p < 16; p++)                                        \
                cp16(sa + p * 16 * ROWB, ag + (long)p * 16 * lda);              \
            if constexpr (!TRANSB) {                                            \
                const __half* bg = Bbase + (long)(itv) * BK;                    \
                _Pragma("unroll")                                               \
                for (int p = 0; p < 8; p++)                                     \
                    cp16(sb + p * 16 * ROWB, bg + (long)p * 16 * ldb);          \
            } else {                                                            \
                const __half* bg = Bbase + (long)(itv) * BK * ldb;              \
                _Pragma("unroll")                                               \
                for (int p = 0; p < 8; p++)                                     \
                    cp16(sb + p * 16 * ROWVB, bg + (long)p * 16 * ldb);         \
            }                                                                   \
        }                                                                       \
        cp_commit();                                                            \
    } while (0)

    // Fragment loaders (ks = 0..KSN-1 selects k16 step within the BK tile).
    auto load_af = [&](uint32_t af[4][4], uint32_t sb, int ks) {
#pragma unroll
        for (int mt = 0; mt < 4; mt++)
            ldsm_x4(af[mt], sb + aoff + (uint32_t)mt * 16 * ROWB + (uint32_t)ks * 32);
    };
    auto load_bf = [&](uint32_t bf[8][2], uint32_t sb, int ks) {
#pragma unroll
        for (int pr = 0; pr < 4; pr++) {
            uint32_t r[4];
            if constexpr (!TRANSB) {
                ldsm_x4(r, sb + boff + (uint32_t)pr * 16 * ROWB + (uint32_t)ks * 32);
            } else {
                ldsm_x4_t(r, sb + boff + (uint32_t)ks * 16 * ROWVB + (uint32_t)pr * 32);
            }
            bf[2 * pr][0]     = r[0]; bf[2 * pr][1]     = r[1];
            bf[2 * pr + 1][0] = r[2]; bf[2 * pr + 1][1] = r[3];
        }
    };

    ISSUE_STAGE(0, 0);

    uint32_t af[2][4][4], bf[2][8][2];

    for (int it = 0; it < n; it++) {
        cp_wait<0>();          // only outstanding group is stage `it` (issued 1 iter ago)
        __syncthreads();

        const uint32_t sb = sbase + (uint32_t)(it & 1) * STAGE_BYTES;

        // Start the LDSM chain immediately after the barrier...
        load_af(af[0], sb, 0);
        load_bf(bf[0], sb, 0);

        // ...then issue next-stage copies (overlap with this iteration's MMAs).
        ISSUE_STAGE((it + 1) & 1, it + 1);

#pragma unroll
        for (int ks = 0; ks < KSN; ks++) {
            const int cur = ks & 1;
            if (ks < KSN - 1) {
                load_af(af[cur ^ 1], sb, ks + 1);
                load_bf(bf[cur ^ 1], sb, ks + 1);
            }
#pragma unroll
            for (int mt = 0; mt < 4; mt++)
#pragma unroll
                for (int nt = 0; nt < 8; nt++)
                    mma_f16(acc[mt][nt], af[cur][mt], bf[cur][nt]);
        }
    }
#undef ISSUE_STAGE

    // Epilogue
#pragma unroll
    for (int mt = 0; mt < 4; mt++) {
#pragma unroll
        for (int nt = 0; nt < 8; nt++) {
            const int m  = bm * BM + wr * 64 + mt * 16 + g;
            const int nn = bn * BN + wc * 64 + nt * 8 + 2 * t;
            if constexpr (sizeof(OutT) == 4) {
                float2 v0 = { acc[mt][nt][0] * alpha, acc[mt][nt][1] * alpha };
                float2 v1 = { acc[mt][nt][2] * alpha, acc[mt][nt][3] * alpha };
                *(float2*)&((float*)C)[(long)m * ldc + nn]       = v0;
                *(float2*)&((float*)C)[(long)(m + 8) * ldc + nn] = v1;
            } else {
                __half2 h0 = __floats2half2_rn(acc[mt][nt][0] * alpha, acc[mt][nt][1] * alpha);
                __half2 h1 = __floats2half2_rn(acc[mt][nt][2] * alpha, acc[mt][nt][3] * alpha);
                *(__half2*)&((__half*)C)[(long)m * ldc + nn]       = h0;
                *(__half2*)&((__half*)C)[(long)(m + 8) * ldc + nn] = h1;
            }
        }
    }
}

#define SMEM_QKV (STAGES * (A_BYTES + BN_BYTES))   // 208896
#define SMEM_PV  (STAGES * (A_BYTES + BT_BYTES))   // 208896

// ---------------------------------------------------------------------------
// Kernels
// ---------------------------------------------------------------------------

__global__ void convx_kernel(const float* __restrict__ src)
{
    const int i = blockIdx.x * blockDim.x + threadIdx.x;
    const int n4 = BATCH * SEQ * DIM / 4;
    if (i < n4) {
        float4 v = ((const float4*)src)[i];
        ((__half2*)g_xh)[2 * i]     = __floats2half2_rn(v.x, v.y);
        ((__half2*)g_xh)[2 * i + 1] = __floats2half2_rn(v.z, v.w);
    }
}

__global__ void convw_kernel(const float* __restrict__ Wq,
                             const float* __restrict__ Wk,
                             const float* __restrict__ Wv)
{
    const float* src = (blockIdx.z == 0) ? Wq : (blockIdx.z == 1) ? Wk : Wv;
    __half* dst = g_wh + (size_t)blockIdx.z * DIM * DIM;
    const int i = blockIdx.x * blockDim.x + threadIdx.x;
    const int n4 = DIM * DIM / 4;
    if (i < n4) {
        float4 v = ((const float4*)src)[i];
        ((__half2*)dst)[2 * i]     = __floats2half2_rn(v.x, v.y);
        ((__half2*)dst)[2 * i + 1] = __floats2half2_rn(v.z, v.w);
    }
}

__global__ void __launch_bounds__(NTHREADS, 1)
qkv_kernel()
{
    const __half* W = g_wh + (size_t)blockIdx.z * DIM * DIM;
    __half* out = (blockIdx.z == 0) ? g_qh : (blockIdx.z == 1) ? g_kh : g_vh;
    gemm_h<__half, false>(g_xh, DIM, W, DIM, out, DIM, DIM, 1.0f, blockIdx.y, blockIdx.x);
}

__global__ void __launch_bounds__(NTHREADS, 1)
qk_kernel()
{
    const int bx = blockIdx.x, by = blockIdx.y, b = blockIdx.z;
    if (bx > 2 * by + 1) return;  // fully-masked causal block (256-row x 128-col)
    const __half* Q = g_qh + (long)b * SEQ * DIM;
    const __half* K = g_kh + (long)b * SEQ * DIM;
    float* S = g_s + (long)b * SEQ * SEQ;
    gemm_h<float, false>(Q, DIM, K, DIM, S, SEQ, DIM, SCALE, by, bx);
}

// Single-pass causal softmax: S (fp32) read once into regs; fp16 P out.
__global__ void __launch_bounds__(256)
softmax_kernel()
{
    const int row = blockIdx.x;
    const int b = row >> 11;
    const int i = row & (SEQ - 1);
    const float* S = g_s + (long)b * SEQ * SEQ + (long)i * SEQ;
    __half* P = g_ph + (long)b * SEQ * SEQ + (long)i * SEQ;
    const int n = i + 1;
    const int tid = threadIdx.x;
    __shared__ float red[256];

    float v[8];
    float lmax = -1e30f;
#pragma unroll
    for (int p = 0; p < 8; p++) {
        const int j = tid + 256 * p;
        v[p] = (j < n) ? S[j] : -1e30f;
        lmax = fmaxf(lmax, v[p]);
    }
    red[tid] = lmax; __syncthreads();
    for (int s = 128; s > 0; s >>= 1) {
        if (tid < s) red[tid] = fmaxf(red[tid], red[tid + s]);
        __syncthreads();
    }
    const float m = red[0]; __syncthreads();

    float lsum = 0.0f;
#pragma unroll
    for (int p = 0; p < 8; p++) {
        const int j = tid + 256 * p;
        v[p] = (j < n) ? __expf(v[p] - m) : 0.0f;
        lsum += v[p];
    }
    red[tid] = lsum; __syncthreads();
    for (int s = 128; s > 0; s >>= 1) {
        if (tid < s) red[tid] += red[tid + s];
        __syncthreads();
    }
    const float inv = 1.0f / red[0];

#pragma unroll
    for (int p = 0; p < 8; p++)
        P[tid + 256 * p] = __float2half(v[p] * inv);
}

__global__ void __launch_bounds__(NTHREADS, 1)
pv_kernel(float* __restrict__ out)
{
    const int bx = blockIdx.x, by = blockIdx.y, b = blockIdx.z;
    const __half* P = g_ph + (long)b * SEQ * SEQ;
    const __half* V = g_vh + (long)b * SEQ * DIM;   // [k=T][n=D], natural layout
    float* O = out + (long)b * SEQ * DIM;
    const int Klim = (by + 1) * BM;   // causal truncation (P tail zeroed); % BK == 0
    gemm_h<float, true>(P, SEQ, V, DIM, O, DIM, Klim, 1.0f, by, bx);
}

// ---------------------------------------------------------------------------
extern "C" void kernel_launch(void* const* d_in, const int* in_sizes, int n_in,
                              void* d_out, int out_size)
{
    const float* x  = (const float*)d_in[0];
    const float* Wq = (const float*)d_in[1];
    const float* Wk = (const float*)d_in[2];
    const float* Wv = (const float*)d_in[3];
    float* out = (float*)d_out;

    cudaFuncSetAttribute(qkv_kernel, cudaFuncAttributeMaxDynamicSharedMemorySize, SMEM_QKV);
    cudaFuncSetAttribute(qk_kernel,  cudaFuncAttributeMaxDynamicSharedMemorySize, SMEM_QKV);
    cudaFuncSetAttribute(pv_kernel,  cudaFuncAttributeMaxDynamicSharedMemorySize, SMEM_PV);

    convx_kernel<<<(BATCH * SEQ * DIM / 4 + 255) / 256, 256>>>(x);
    convw_kernel<<<dim3(DIM * DIM / 4 / 256, 1, 3), 256>>>(Wq, Wk, Wv);

    dim3 g_qkv(DIM / BN, (BATCH * SEQ) / BM, 3);        // (8, 32, 3)
    qkv_kernel<<<g_qkv, NTHREADS, SMEM_QKV>>>();

    dim3 g_qk(SEQ / BN, SEQ / BM, BATCH);               // (16, 8, 4)
    qk_kernel<<<g_qk, NTHREADS, SMEM_QKV>>>();

    softmax_kernel<<<BATCH * SEQ, 256>>>();

    dim3 g_pv(DIM / BN, SEQ / BM, BATCH);               // (8, 8, 4)
    pv_kernel<<<g_pv, NTHREADS, SMEM_PV>>>(out);
}

// round 16
// speedup vs baseline: 1.0615x; 1.0615x over previous
#include <cuda_runtime.h>
#include <cuda_fp16.h>
#include <cstdint>

// Problem constants
#define BATCH 4
#define SEQ   2048
#define DIM   1024
#define SCALE 0.03125f   // 1024^-0.5

// GEMM tile config (fp16 mma.sync m16n8k16, cp.async multistage) — R11 config
#define BM 256                             // CTA rows
#define BN 128                             // CTA cols
#define BK 64                              // halfs per k-chunk (128B rows)
#define STAGES 3
#define NTHREADS 256
#define ROWB 144                           // [*,K] row bytes (128 data + 16 pad); 36w % 32 = 4 -> conflict-free
#define ROWVB 272                          // [K,N] row bytes (256 data + 16 pad); 68w % 32 = 4 -> conflict-free
#define A_BYTES (BM * ROWB)                // 36864
#define BN_BYTES (BN * ROWB)               // 18432 (non-trans B tile)
#define BT_BYTES (BK * ROWVB)              // 17408 (trans B tile)

// Scratch (device globals: allocation-free rule)
static __device__ __half g_xh[BATCH * SEQ * DIM];
static __device__ __half g_wh[3 * DIM * DIM];
static __device__ __half g_qh[BATCH * SEQ * DIM];
static __device__ __half g_kh[BATCH * SEQ * DIM];
static __device__ __half g_vh[BATCH * SEQ * DIM];
static __device__ float  g_s[(size_t)BATCH * SEQ * SEQ];
static __device__ __half g_ph[(size_t)BATCH * SEQ * SEQ];

// ---------------------------------------------------------------------------
// helpers
// ---------------------------------------------------------------------------
static __device__ __forceinline__ uint32_t smem_u32(const void* p) {
    uint32_t a;
    asm("{ .reg .u64 t; cvta.to.shared.u64 t, %1; cvt.u32.u64 %0, t; }" : "=r"(a) : "l"(p));
    return a;
}

static __device__ __forceinline__ void ldsm_x4(uint32_t* r, uint32_t addr) {
    asm volatile("ldmatrix.sync.aligned.m8n8.x4.shared.b16 {%0,%1,%2,%3}, [%4];"
                 : "=r"(r[0]), "=r"(r[1]), "=r"(r[2]), "=r"(r[3]) : "r"(addr));
}
static __device__ __forceinline__ void ldsm_x4_t(uint32_t* r, uint32_t addr) {
    asm volatile("ldmatrix.sync.aligned.m8n8.x4.trans.shared.b16 {%0,%1,%2,%3}, [%4];"
                 : "=r"(r[0]), "=r"(r[1]), "=r"(r[2]), "=r"(r[3]) : "r"(addr));
}

static __device__ __forceinline__ void mma_f16(float* c, const uint32_t* a, const uint32_t* b) {
    asm volatile(
        "mma.sync.aligned.m16n8k16.row.col.f32.f16.f16.f32 "
        "{%0,%1,%2,%3}, {%4,%5,%6,%7}, {%8,%9}, {%0,%1,%2,%3};\n"
        : "+f"(c[0]), "+f"(c[1]), "+f"(c[2]), "+f"(c[3])
        : "r"(a[0]), "r"(a[1]), "r"(a[2]), "r"(a[3]),
          "r"(b[0]), "r"(b[1]));
}

static __device__ __forceinline__ void cp16(uint32_t dst, const void* src) {
    asm volatile("cp.async.ca.shared.global [%0], [%1], 16;" :: "r"(dst), "l"(src) : "memory");
}
static __device__ __forceinline__ void cp_commit() {
    asm volatile("cp.async.commit_group;" ::: "memory");
}
template <int N>
static __device__ __forceinline__ void cp_wait() {
    asm volatile("cp.async.wait_group %0;" :: "n"(N) : "memory");
}

// ---------------------------------------------------------------------------
// TN/NN GEMM (fp16 mma.sync m16n8k16, multistage cp.async, frag double-buffer):
//   TRANSB=false: C[m,n] = alpha * sum_k A[m,k] * B[n,k]   (B: [N,K], ldb)
//   TRANSB=true : C[m,n] = alpha * sum_k A[m,k] * B[k,n]   (B: [K,N], ldb)
// A: [M,K] half, K-contiguous. fp32 accumulation. Klim % BK == 0.
// 256x128 CTA tile, 8 warps (4x2), warp tile 64x64; BK=64 -> 4 k16-steps/iter.
// ---------------------------------------------------------------------------
template <typename OutT, bool TRANSB>
static __device__ __forceinline__ void gemm_h(
    const __half* __restrict__ A, int lda,
    const __half* __restrict__ B, int ldb,
    OutT* __restrict__ C, int ldc,
    int Klim, float alpha, int bm, int bn)
{
    constexpr uint32_t B_BYTES = TRANSB ? BT_BYTES : BN_BYTES;
    constexpr uint32_t STAGE_BYTES = A_BYTES + B_BYTES;

    extern __shared__ char smem[];
    const uint32_t sbase = smem_u32(smem);

    const int tid  = threadIdx.x;
    const int warp = tid >> 5;
    const int lane = tid & 31;
    const int wr = warp >> 1;          // 0..3: warp row (64-row band of 256)
    const int wc = warp & 1;           // 0..1: warp col (64-col band of 128)
    const int g  = lane >> 2;
    const int t  = lane & 3;

    // A staging: rows (tid>>3)+{0,32,...,224}, 16B segment (tid&7). 8 cp16/thread.
    const int arow = tid >> 3;         // 0..31
    const int aseg = tid & 7;          // 0..7
    const __half* Abase = A + (long)(bm * BM + arow) * lda + aseg * 8;
    const uint32_t soffA = (uint32_t)arow * ROWB + (uint32_t)aseg * 16;

    // B staging:
    //  non-trans: rows (tid>>3)+{0,32,64,96} over [N,K]. 4 cp16/thread.
    //  trans: tile [BK=64 k rows][256B n], rows (tid>>4)+{0,16,32,48}, seg tid&15.
    const __half* Bbase;
    uint32_t soffB;
    if constexpr (!TRANSB) {
        Bbase = B + (long)(bn * BN + arow) * ldb + aseg * 8;
        soffB = soffA;
    } else {
        const int vrow = tid >> 4;     // 0..15
        const int vseg = tid & 15;     // 0..15 (8 halfs each)
        Bbase = B + (long)vrow * ldb + bn * BN + vseg * 8;
        soffB = (uint32_t)vrow * ROWVB + (uint32_t)vseg * 16;
    }

    // ldmatrix per-lane byte offsets (within a stage buffer).
    const uint32_t aoff = (uint32_t)(wr * 64 + (lane & 15)) * ROWB + (uint32_t)(lane >> 4) * 16;
    uint32_t boff;
    if constexpr (!TRANSB) {
        boff = A_BYTES
            + (uint32_t)(wc * 64 + (lane & 7) + ((lane & 16) ? 8 : 0)) * ROWB
            + (uint32_t)((lane >> 3) & 1) * 16;
    } else {
        // trans: lanes 0-15 -> k=lane&15, n-col +0; lanes 16-31 -> n-col +8.
        boff = A_BYTES
            + (uint32_t)(lane & 15) * ROWVB
            + (uint32_t)(wc * 64 + ((lane >> 4) ? 8 : 0)) * 2;
    }

    float acc[4][8][4];
#pragma unroll
    for (int i = 0; i < 4; i++)
#pragma unroll
        for (int j = 0; j < 8; j++)
#pragma unroll
            for (int r = 0; r < 4; r++) acc[i][j][r] = 0.0f;

    const int n = Klim / BK;

#define ISSUE_STAGE(stage, itv)                                                 \
    do {                                                                        \
        if ((itv) < n) {                                                        \
            const uint32_t sa = sbase + (uint32_t)(stage) * STAGE_BYTES + soffA;\
            const uint32_t sb = sbase + (uint32_t)(stage) * STAGE_BYTES         \
                              + A_BYTES + soffB;                                \
            const __half* ag = Abase + (long)(itv) * BK;                        \
            _Pragma("unroll")                                                   \
            for (int p = 0; p < 8; p++)                                         \
                cp16(sa + p * 32 * ROWB, ag + (long)p * 32 * lda);              \
            if constexpr (!TRANSB) {                                            \
                const __half* bg = Bbase + (long)(itv) * BK;                    \
                _Pragma("unroll")                                               \
                for (int p = 0; p < 4; p++)                                     \
                    cp16(sb + p * 32 * ROWB, bg + (long)p * 32 * ldb);          \
            } else {                                                            \
                const __half* bg = Bbase + (long)(itv) * BK * ldb;              \
                _Pragma("unroll")                                               \
                for (int p = 0; p < 4; p++)                                     \
                    cp16(sb + p * 16 * ROWVB, bg + (long)p * 16 * ldb);         \
            }                                                                   \
        }                                                                       \
        cp_commit();                                                            \
    } while (0)

    // Fragment loaders (ks = 0..3 selects k16 step within the BK=64 tile).
    auto load_af = [&](uint32_t af[4][4], uint32_t sb, int ks) {
#pragma unroll
        for (int mt = 0; mt < 4; mt++)
            ldsm_x4(af[mt], sb + aoff + (uint32_t)mt * 16 * ROWB + (uint32_t)ks * 32);
    };
    auto load_bf = [&](uint32_t bf[8][2], uint32_t sb, int ks) {
#pragma unroll
        for (int pr = 0; pr < 4; pr++) {
            uint32_t r[4];
            if constexpr (!TRANSB) {
                ldsm_x4(r, sb + boff + (uint32_t)pr * 16 * ROWB + (uint32_t)ks * 32);
            } else {
                ldsm_x4_t(r, sb + boff + (uint32_t)ks * 16 * ROWVB + (uint32_t)pr * 32);
            }
            bf[2 * pr][0]     = r[0]; bf[2 * pr][1]     = r[1];
            bf[2 * pr + 1][0] = r[2]; bf[2 * pr + 1][1] = r[3];
        }
    };

#pragma unroll
    for (int s = 0; s < STAGES - 1; s++) ISSUE_STAGE(s, s);

    uint32_t af[2][4][4], bf[2][8][2];

    for (int it = 0; it < n; it++) {
        cp_wait<STAGES - 2>();
        __syncthreads();

        ISSUE_STAGE((it + STAGES - 1) % STAGES, it + STAGES - 1);

        const uint32_t sb = sbase + (uint32_t)(it % STAGES) * STAGE_BYTES;

        load_af(af[0], sb, 0);
        load_bf(bf[0], sb, 0);

#pragma unroll
        for (int ks = 0; ks < 4; ks++) {
            const int cur = ks & 1;
            if (ks < 3) {
                load_af(af[cur ^ 1], sb, ks + 1);
                load_bf(bf[cur ^ 1], sb, ks + 1);
            }
#pragma unroll
            for (int mt = 0; mt < 4; mt++)
#pragma unroll
                for (int nt = 0; nt < 8; nt++)
                    mma_f16(acc[mt][nt], af[cur][mt], bf[cur][nt]);
        }
    }
#undef ISSUE_STAGE

    // Epilogue
#pragma unroll
    for (int mt = 0; mt < 4; mt++) {
#pragma unroll
        for (int nt = 0; nt < 8; nt++) {
            const int m  = bm * BM + wr * 64 + mt * 16 + g;
            const int nn = bn * BN + wc * 64 + nt * 8 + 2 * t;
            if constexpr (sizeof(OutT) == 4) {
                float2 v0 = { acc[mt][nt][0] * alpha, acc[mt][nt][1] * alpha };
                float2 v1 = { acc[mt][nt][2] * alpha, acc[mt][nt][3] * alpha };
                *(float2*)&((float*)C)[(long)m * ldc + nn]       = v0;
                *(float2*)&((float*)C)[(long)(m + 8) * ldc + nn] = v1;
            } else {
                __half2 h0 = __floats2half2_rn(acc[mt][nt][0] * alpha, acc[mt][nt][1] * alpha);
                __half2 h1 = __floats2half2_rn(acc[mt][nt][2] * alpha, acc[mt][nt][3] * alpha);
                *(__half2*)&((__half*)C)[(long)m * ldc + nn]       = h0;
                *(__half2*)&((__half*)C)[(long)(m + 8) * ldc + nn] = h1;
            }
        }
    }
}

#define SMEM_QKV (STAGES * (A_BYTES + BN_BYTES))   // 165888
#define SMEM_PV  (STAGES * (A_BYTES + BT_BYTES))   // 162816

// ---------------------------------------------------------------------------
// Kernels
// ---------------------------------------------------------------------------

// Merged fp32->fp16 convert for x, Wq, Wk, Wv (single launch).
#define XN4 (BATCH * SEQ * DIM / 4)    // 2097152 float4s
#define WN4 (DIM * DIM / 4)            // 262144 float4s each

__global__ void conv_all_kernel(const float* __restrict__ x,
                                const float* __restrict__ Wq,
                                const float* __restrict__ Wk,
                                const float* __restrict__ Wv)
{
    const int i = blockIdx.x * blockDim.x + threadIdx.x;
    const float* src;
    __half2* dst;
    int off;
    if (i < XN4) {
        src = x; dst = (__half2*)g_xh; off = i;
    } else {
        const int w = i - XN4;
        if (w >= 3 * WN4) return;
        const int which = w / WN4;
        off = w - which * WN4;
        src = (which == 0) ? Wq : (which == 1) ? Wk : Wv;
        dst = (__half2*)(g_wh + (size_t)which * DIM * DIM);
    }
    float4 v = ((const float4*)src)[off];
    dst[2 * off]     = __floats2half2_rn(v.x, v.y);
    dst[2 * off + 1] = __floats2half2_rn(v.z, v.w);
}

__global__ void __launch_bounds__(NTHREADS, 1)
qkv_kernel()
{
    const __half* W = g_wh + (size_t)blockIdx.z * DIM * DIM;
    __half* out = (blockIdx.z == 0) ? g_qh : (blockIdx.z == 1) ? g_kh : g_vh;
    gemm_h<__half, false>(g_xh, DIM, W, DIM, out, DIM, DIM, 1.0f, blockIdx.y, blockIdx.x);
}

__global__ void __launch_bounds__(NTHREADS, 1)
qk_kernel()
{
    const int bx = blockIdx.x, by = blockIdx.y, b = blockIdx.z;
    if (bx > 2 * by + 1) return;  // fully-masked causal block (256-row x 128-col)
    const __half* Q = g_qh + (long)b * SEQ * DIM;
    const __half* K = g_kh + (long)b * SEQ * DIM;
    float* S = g_s + (long)b * SEQ * SEQ;
    gemm_h<float, false>(Q, DIM, K, DIM, S, SEQ, DIM, SCALE, by, bx);
}

// Single-pass causal softmax, vectorized: two float4 loads + one uint4 store
// per thread; loads beyond the causal bound are skipped entirely.
__global__ void __launch_bounds__(256)
softmax_kernel()
{
    const int row = blockIdx.x;
    const int b = row >> 11;
    const int i = row & (SEQ - 1);
    const float* S = g_s + (long)b * SEQ * SEQ + (long)i * SEQ;
    __half* P = g_ph + (long)b * SEQ * SEQ + (long)i * SEQ;
    const int n = i + 1;
    const int tid = threadIdx.x;
    const int j0 = tid * 8;
    __shared__ float red[256];

    float v[8];
    if (j0 + 8 <= n) {
        float4 a = ((const float4*)S)[2 * tid];
        float4 c = ((const float4*)S)[2 * tid + 1];
        v[0] = a.x; v[1] = a.y; v[2] = a.z; v[3] = a.w;
        v[4] = c.x; v[5] = c.y; v[6] = c.z; v[7] = c.w;
    } else {
#pragma unroll
        for (int e = 0; e < 8; e++)
            v[e] = (j0 + e < n) ? S[j0 + e] : -1e30f;
    }

    float lmax = -1e30f;
#pragma unroll
    for (int e = 0; e < 8; e++) lmax = fmaxf(lmax, v[e]);
    red[tid] = lmax; __syncthreads();
    for (int s = 128; s > 0; s >>= 1) {
        if (tid < s) red[tid] = fmaxf(red[tid], red[tid + s]);
        __syncthreads();
    }
    const float m = red[0]; __syncthreads();

    float lsum = 0.0f;
#pragma unroll
    for (int e = 0; e < 8; e++) {
        v[e] = (j0 + e < n) ? __expf(v[e] - m) : 0.0f;
        lsum += v[e];
    }
    red[tid] = lsum; __syncthreads();
    for (int s = 128; s > 0; s >>= 1) {
        if (tid < s) red[tid] += red[tid + s];
        __syncthreads();
    }
    const float inv = 1.0f / red[0];

    uint4 pk;
    __half2* ph = (__half2*)&pk;
#pragma unroll
    for (int e = 0; e < 4; e++)
        ph[e] = __floats2half2_rn(v[2 * e] * inv, v[2 * e + 1] * inv);
    ((uint4*)P)[tid] = pk;
}

__global__ void __launch_bounds__(NTHREADS, 1)
pv_kernel(float* __restrict__ out)
{
    const int bx = blockIdx.x, by = blockIdx.y, b = blockIdx.z;
    const __half* P = g_ph + (long)b * SEQ * SEQ;
    const __half* V = g_vh + (long)b * SEQ * DIM;   // [k=T][n=D], natural layout
    float* O = out + (long)b * SEQ * DIM;
    const int Klim = (by + 1) * BM;   // causal truncation (P tail zeroed); % BK == 0
    gemm_h<float, true>(P, SEQ, V, DIM, O, DIM, Klim, 1.0f, by, bx);
}

// ---------------------------------------------------------------------------
extern "C" void kernel_launch(void* const* d_in, const int* in_sizes, int n_in,
                              void* d_out, int out_size)
{
    const float* x  = (const float*)d_in[0];
    const float* Wq = (const float*)d_in[1];
    const float* Wk = (const float*)d_in[2];
    const float* Wv = (const float*)d_in[3];
    float* out = (float*)d_out;

    cudaFuncSetAttribute(qkv_kernel, cudaFuncAttributeMaxDynamicSharedMemorySize, SMEM_QKV);
    cudaFuncSetAttribute(qk_kernel,  cudaFuncAttributeMaxDynamicSharedMemorySize, SMEM_QKV);
    cudaFuncSetAttribute(pv_kernel,  cudaFuncAttributeMaxDynamicSharedMemorySize, SMEM_PV);

    conv_all_kernel<<<(XN4 + 3 * WN4 + 255) / 256, 256>>>(x, Wq, Wk, Wv);

    dim3 g_qkv(DIM / BN, (BATCH * SEQ) / BM, 3);        // (8, 32, 3)
    qkv_kernel<<<g_qkv, NTHREADS, SMEM_QKV>>>();

    dim3 g_qk(SEQ / BN, SEQ / BM, BATCH);               // (16, 8, 4)
    qk_kernel<<<g_qk, NTHREADS, SMEM_QKV>>>();

    softmax_kernel<<<BATCH * SEQ, 256>>>();

    dim3 g_pv(DIM / BN, SEQ / BM, BATCH);               // (8, 8, 4)
    pv_kernel<<<g_pv, NTHREADS, SMEM_PV>>>(out);
}

// round 17
// speedup vs baseline: 1.0885x; 1.0255x over previous
#include <cuda_runtime.h>
#include <cuda_fp16.h>
#include <cstdint>

// Problem constants
#define BATCH 4
#define SEQ   2048
#define DIM   1024
#define SCALE 0.03125f   // 1024^-0.5

// GEMM tile config: 128x128 CTA tile, 4 warps (2x2) of 64x64, 2 CTAs/SM.
#define BM 128                             // CTA rows
#define BN 128                             // CTA cols
#define BK 64                              // halfs per k-chunk (128B rows)
#define STAGES 3
#define NTHREADS 128
#define ROWB 144                           // [*,K] row bytes (128 data + 16 pad); 36w % 32 = 4 -> conflict-free
#define ROWVB 272                          // [K,N] row bytes (256 data + 16 pad); 68w % 32 = 4 -> conflict-free
#define A_BYTES (BM * ROWB)                // 18432
#define BN_BYTES (BN * ROWB)               // 18432 (non-trans B tile)
#define BT_BYTES (BK * ROWVB)              // 17408 (trans B tile)

// Scratch (device globals: allocation-free rule)
static __device__ __half g_xh[BATCH * SEQ * DIM];
static __device__ __half g_wh[3 * DIM * DIM];
static __device__ __half g_qh[BATCH * SEQ * DIM];
static __device__ __half g_kh[BATCH * SEQ * DIM];
static __device__ __half g_vh[BATCH * SEQ * DIM];
static __device__ float  g_s[(size_t)BATCH * SEQ * SEQ];
static __device__ __half g_ph[(size_t)BATCH * SEQ * SEQ];

// ---------------------------------------------------------------------------
// helpers
// ---------------------------------------------------------------------------
static __device__ __forceinline__ uint32_t smem_u32(const void* p) {
    uint32_t a;
    asm("{ .reg .u64 t; cvta.to.shared.u64 t, %1; cvt.u32.u64 %0, t; }" : "=r"(a) : "l"(p));
    return a;
}

static __device__ __forceinline__ void ldsm_x4(uint32_t* r, uint32_t addr) {
    asm volatile("ldmatrix.sync.aligned.m8n8.x4.shared.b16 {%0,%1,%2,%3}, [%4];"
                 : "=r"(r[0]), "=r"(r[1]), "=r"(r[2]), "=r"(r[3]) : "r"(addr));
}
static __device__ __forceinline__ void ldsm_x4_t(uint32_t* r, uint32_t addr) {
    asm volatile("ldmatrix.sync.aligned.m8n8.x4.trans.shared.b16 {%0,%1,%2,%3}, [%4];"
                 : "=r"(r[0]), "=r"(r[1]), "=r"(r[2]), "=r"(r[3]) : "r"(addr));
}

static __device__ __forceinline__ void mma_f16(float* c, const uint32_t* a, const uint32_t* b) {
    asm volatile(
        "mma.sync.aligned.m16n8k16.row.col.f32.f16.f16.f32 "
        "{%0,%1,%2,%3}, {%4,%5,%6,%7}, {%8,%9}, {%0,%1,%2,%3};\n"
        : "+f"(c[0]), "+f"(c[1]), "+f"(c[2]), "+f"(c[3])
        : "r"(a[0]), "r"(a[1]), "r"(a[2]), "r"(a[3]),
          "r"(b[0]), "r"(b[1]));
}

static __device__ __forceinline__ void cp16(uint32_t dst, const void* src) {
    asm volatile("cp.async.ca.shared.global [%0], [%1], 16;" :: "r"(dst), "l"(src) : "memory");
}
static __device__ __forceinline__ void cp_commit() {
    asm volatile("cp.async.commit_group;" ::: "memory");
}
template <int N>
static __device__ __forceinline__ void cp_wait() {
    asm volatile("cp.async.wait_group %0;" :: "n"(N) : "memory");
}

// ---------------------------------------------------------------------------
// TN/NN GEMM (fp16 mma.sync m16n8k16, 3-stage cp.async, frag double-buffer):
//   TRANSB=false: C[m,n] = alpha * sum_k A[m,k] * B[n,k]   (B: [N,K], ldb)
//   TRANSB=true : C[m,n] = alpha * sum_k A[m,k] * B[k,n]   (B: [K,N], ldb)
// A: [M,K] half, K-contiguous. fp32 accumulation. Klim % BK == 0.
// 128x128 CTA tile, 4 warps (2x2), warp tile 64x64; BK=64 -> 4 k16-steps/iter.
// 128 threads, 2 CTAs/SM (smem 110.6KB/CTA) -> interleaved barriers across CTAs.
// ---------------------------------------------------------------------------
template <typename OutT, bool TRANSB>
static __device__ __forceinline__ void gemm_h(
    const __half* __restrict__ A, int lda,
    const __half* __restrict__ B, int ldb,
    OutT* __restrict__ C, int ldc,
    int Klim, float alpha, int bm, int bn)
{
    constexpr uint32_t B_BYTES = TRANSB ? BT_BYTES : BN_BYTES;
    constexpr uint32_t STAGE_BYTES = A_BYTES + B_BYTES;

    extern __shared__ char smem[];
    const uint32_t sbase = smem_u32(smem);

    const int tid  = threadIdx.x;
    const int warp = tid >> 5;
    const int lane = tid & 31;
    const int wr = warp >> 1;          // 0..1: warp row (64-row band of 128)
    const int wc = warp & 1;           // 0..1: warp col (64-col band of 128)
    const int g  = lane >> 2;
    const int t  = lane & 3;

    // A staging: rows (tid>>3)+{0,16,...,112}, 16B segment (tid&7). 8 cp16/thread.
    const int arow = tid >> 3;         // 0..15
    const int aseg = tid & 7;          // 0..7
    const __half* Abase = A + (long)(bm * BM + arow) * lda + aseg * 8;
    const uint32_t soffA = (uint32_t)arow * ROWB + (uint32_t)aseg * 16;

    // B staging:
    //  non-trans: rows (tid>>3)+{0,16,...,112} over [N,K]. 8 cp16/thread.
    //  trans: tile [BK=64 k rows][256B n], rows (tid>>4)+{0,8,...,56}, seg tid&15.
    const __half* Bbase;
    uint32_t soffB;
    if constexpr (!TRANSB) {
        Bbase = B + (long)(bn * BN + arow) * ldb + aseg * 8;
        soffB = soffA;
    } else {
        const int vrow = tid >> 4;     // 0..7
        const int vseg = tid & 15;     // 0..15 (8 halfs each)
        Bbase = B + (long)vrow * ldb + bn * BN + vseg * 8;
        soffB = (uint32_t)vrow * ROWVB + (uint32_t)vseg * 16;
    }

    // ldmatrix per-lane byte offsets (within a stage buffer).
    const uint32_t aoff = (uint32_t)(wr * 64 + (lane & 15)) * ROWB + (uint32_t)(lane >> 4) * 16;
    uint32_t boff;
    if constexpr (!TRANSB) {
        boff = A_BYTES
            + (uint32_t)(wc * 64 + (lane & 7) + ((lane & 16) ? 8 : 0)) * ROWB
            + (uint32_t)((lane >> 3) & 1) * 16;
    } else {
        // trans: lanes 0-15 -> k=lane&15, n-col +0; lanes 16-31 -> n-col +8.
        boff = A_BYTES
            + (uint32_t)(lane & 15) * ROWVB
            + (uint32_t)(wc * 64 + ((lane >> 4) ? 8 : 0)) * 2;
    }

    float acc[4][8][4];
#pragma unroll
    for (int i = 0; i < 4; i++)
#pragma unroll
        for (int j = 0; j < 8; j++)
#pragma unroll
            for (int r = 0; r < 4; r++) acc[i][j][r] = 0.0f;

    const int n = Klim / BK;

#define ISSUE_STAGE(stage, itv)                                                 \
    do {                                                                        \
        if ((itv) < n) {                                                        \
            const uint32_t sa = sbase + (uint32_t)(stage) * STAGE_BYTES + soffA;\
            const uint32_t sb = sbase + (uint32_t)(stage) * STAGE_BYTES         \
                              + A_BYTES + soffB;                                \
            const __half* ag = Abase + (long)(itv) * BK;                        \
            _Pragma("unroll")                                                   \
            for (int p = 0; p < 8; p++)                                         \
                cp16(sa + p * 16 * ROWB, ag + (long)p * 16 * lda);              \
            if constexpr (!TRANSB) {                                            \
                const __half* bg = Bbase + (long)(itv) * BK;                    \
                _Pragma("unroll")                                               \
                for (int p = 0; p < 8; p++)                                     \
                    cp16(sb + p * 16 * ROWB, bg + (long)p * 16 * ldb);          \
            } else {                                                            \
                const __half* bg = Bbase + (long)(itv) * BK * ldb;              \
                _Pragma("unroll")                                               \
                for (int p = 0; p < 8; p++)                                     \
                    cp16(sb + p * 8 * ROWVB, bg + (long)p * 8 * ldb);           \
            }                                                                   \
        }                                                                       \
        cp_commit();                                                            \
    } while (0)

    // Fragment loaders (ks = 0..3 selects k16 step within the BK=64 tile).
    auto load_af = [&](uint32_t af[4][4], uint32_t sb, int ks) {
#pragma unroll
        for (int mt = 0; mt < 4; mt++)
            ldsm_x4(af[mt], sb + aoff + (uint32_t)mt * 16 * ROWB + (uint32_t)ks * 32);
    };
    auto load_bf = [&](uint32_t bf[8][2], uint32_t sb, int ks) {
#pragma unroll
        for (int pr = 0; pr < 4; pr++) {
            uint32_t r[4];
            if constexpr (!TRANSB) {
                ldsm_x4(r, sb + boff + (uint32_t)pr * 16 * ROWB + (uint32_t)ks * 32);
            } else {
                ldsm_x4_t(r, sb + boff + (uint32_t)ks * 16 * ROWVB + (uint32_t)pr * 32);
            }
            bf[2 * pr][0]     = r[0]; bf[2 * pr][1]     = r[1];
            bf[2 * pr + 1][0] = r[2]; bf[2 * pr + 1][1] = r[3];
        }
    };

#pragma unroll
    for (int s = 0; s < STAGES - 1; s++) ISSUE_STAGE(s, s);

    uint32_t af[2][4][4], bf[2][8][2];

    for (int it = 0; it < n; it++) {
        cp_wait<STAGES - 2>();
        __syncthreads();

        ISSUE_STAGE((it + STAGES - 1) % STAGES, it + STAGES - 1);

        const uint32_t sb = sbase + (uint32_t)(it % STAGES) * STAGE_BYTES;

        load_af(af[0], sb, 0);
        load_bf(bf[0], sb, 0);

#pragma unroll
        for (int ks = 0; ks < 4; ks++) {
            const int cur = ks & 1;
            if (ks < 3) {
                load_af(af[cur ^ 1], sb, ks + 1);
                load_bf(bf[cur ^ 1], sb, ks + 1);
            }
#pragma unroll
            for (int mt = 0; mt < 4; mt++)
#pragma unroll
                for (int nt = 0; nt < 8; nt++)
                    mma_f16(acc[mt][nt], af[cur][mt], bf[cur][nt]);
        }
    }
#undef ISSUE_STAGE

    // Epilogue
#pragma unroll
    for (int mt = 0; mt < 4; mt++) {
#pragma unroll
        for (int nt = 0; nt < 8; nt++) {
            const int m  = bm * BM + wr * 64 + mt * 16 + g;
            const int nn = bn * BN + wc * 64 + nt * 8 + 2 * t;
            if constexpr (sizeof(OutT) == 4) {
                float2 v0 = { acc[mt][nt][0] * alpha, acc[mt][nt][1] * alpha };
                float2 v1 = { acc[mt][nt][2] * alpha, acc[mt][nt][3] * alpha };
                *(float2*)&((float*)C)[(long)m * ldc + nn]       = v0;
                *(float2*)&((float*)C)[(long)(m + 8) * ldc + nn] = v1;
            } else {
                __half2 h0 = __floats2half2_rn(acc[mt][nt][0] * alpha, acc[mt][nt][1] * alpha);
                __half2 h1 = __floats2half2_rn(acc[mt][nt][2] * alpha, acc[mt][nt][3] * alpha);
                *(__half2*)&((__half*)C)[(long)m * ldc + nn]       = h0;
                *(__half2*)&((__half*)C)[(long)(m + 8) * ldc + nn] = h1;
            }
        }
    }
}

#define SMEM_QKV (STAGES * (A_BYTES + BN_BYTES))   // 110592
#define SMEM_PV  (STAGES * (A_BYTES + BT_BYTES))   // 107520

// ---------------------------------------------------------------------------
// Kernels
// ---------------------------------------------------------------------------

// Merged fp32->fp16 convert for x, Wq, Wk, Wv (single launch).
#define XN4 (BATCH * SEQ * DIM / 4)    // 2097152 float4s
#define WN4 (DIM * DIM / 4)            // 262144 float4s each

__global__ void conv_all_kernel(const float* __restrict__ x,
                                const float* __restrict__ Wq,
                                const float* __restrict__ Wk,
                                const float* __restrict__ Wv)
{
    const int i = blockIdx.x * blockDim.x + threadIdx.x;
    const float* src;
    __half2* dst;
    int off;
    if (i < XN4) {
        src = x; dst = (__half2*)g_xh; off = i;
    } else {
        const int w = i - XN4;
        if (w >= 3 * WN4) return;
        const int which = w / WN4;
        off = w - which * WN4;
        src = (which == 0) ? Wq : (which == 1) ? Wk : Wv;
        dst = (__half2*)(g_wh + (size_t)which * DIM * DIM);
    }
    float4 v = ((const float4*)src)[off];
    dst[2 * off]     = __floats2half2_rn(v.x, v.y);
    dst[2 * off + 1] = __floats2half2_rn(v.z, v.w);
}

__global__ void __launch_bounds__(NTHREADS, 2)
qkv_kernel()
{
    const __half* W = g_wh + (size_t)blockIdx.z * DIM * DIM;
    __half* out = (blockIdx.z == 0) ? g_qh : (blockIdx.z == 1) ? g_kh : g_vh;
    gemm_h<__half, false>(g_xh, DIM, W, DIM, out, DIM, DIM, 1.0f, blockIdx.y, blockIdx.x);
}

__global__ void __launch_bounds__(NTHREADS, 2)
qk_kernel()
{
    const int bx = blockIdx.x, by = blockIdx.y, b = blockIdx.z;
    if (bx > by) return;  // fully-masked causal block (128x128)
    const __half* Q = g_qh + (long)b * SEQ * DIM;
    const __half* K = g_kh + (long)b * SEQ * DIM;
    float* S = g_s + (long)b * SEQ * SEQ;
    gemm_h<float, false>(Q, DIM, K, DIM, S, SEQ, DIM, SCALE, by, bx);
}

// Single-pass causal softmax, vectorized loads + warp-shuffle reductions.
__global__ void __launch_bounds__(256)
softmax_kernel()
{
    const int row = blockIdx.x;
    const int b = row >> 11;
    const int i = row & (SEQ - 1);
    const float* S = g_s + (long)b * SEQ * SEQ + (long)i * SEQ;
    __half* P = g_ph + (long)b * SEQ * SEQ + (long)i * SEQ;
    const int n = i + 1;
    const int tid = threadIdx.x;
    const int wid = tid >> 5;
    const int lane = tid & 31;
    const int j0 = tid * 8;
    __shared__ float redm[8];
    __shared__ float reds[8];

    float v[8];
    if (j0 + 8 <= n) {
        float4 a = ((const float4*)S)[2 * tid];
        float4 c = ((const float4*)S)[2 * tid + 1];
        v[0] = a.x; v[1] = a.y; v[2] = a.z; v[3] = a.w;
        v[4] = c.x; v[5] = c.y; v[6] = c.z; v[7] = c.w;
    } else {
#pragma unroll
        for (int e = 0; e < 8; e++)
            v[e] = (j0 + e < n) ? S[j0 + e] : -1e30f;
    }

    float lmax = -1e30f;
#pragma unroll
    for (int e = 0; e < 8; e++) lmax = fmaxf(lmax, v[e]);
#pragma unroll
    for (int o = 16; o > 0; o >>= 1)
        lmax = fmaxf(lmax, __shfl_xor_sync(0xFFFFFFFFu, lmax, o));
    if (lane == 0) redm[wid] = lmax;
    __syncthreads();
    float m = redm[0];
#pragma unroll
    for (int w = 1; w < 8; w++) m = fmaxf(m, redm[w]);

    float lsum = 0.0f;
#pragma unroll
    for (int e = 0; e < 8; e++) {
        v[e] = (j0 + e < n) ? __expf(v[e] - m) : 0.0f;
        lsum += v[e];
    }
#pragma unroll
    for (int o = 16; o > 0; o >>= 1)
        lsum += __shfl_xor_sync(0xFFFFFFFFu, lsum, o);
    if (lane == 0) reds[wid] = lsum;
    __syncthreads();
    float tot = 0.0f;
#pragma unroll
    for (int w = 0; w < 8; w++) tot += reds[w];
    const float inv = 1.0f / tot;

    uint4 pk;
    __half2* ph = (__half2*)&pk;
#pragma unroll
    for (int e = 0; e < 4; e++)
        ph[e] = __floats2half2_rn(v[2 * e] * inv, v[2 * e + 1] * inv);
    ((uint4*)P)[tid] = pk;
}

__global__ void __launch_bounds__(NTHREADS, 2)
pv_kernel(float* __restrict__ out)
{
    const int bx = blockIdx.x, b = blockIdx.z;
    // Longest-K CTAs first (work-steal scheduler packs the imbalanced tail).
    const int by = (int)gridDim.y - 1 - (int)blockIdx.y;
    const __half* P = g_ph + (long)b * SEQ * SEQ;
    const __half* V = g_vh + (long)b * SEQ * DIM;   // [k=T][n=D], natural layout
    float* O = out + (long)b * SEQ * DIM;
    const int Klim = (by + 1) * BM;   // causal truncation (P tail zeroed); % BK == 0
    gemm_h<float, true>(P, SEQ, V, DIM, O, DIM, Klim, 1.0f, by, bx);
}

// ---------------------------------------------------------------------------
extern "C" void kernel_launch(void* const* d_in, const int* in_sizes, int n_in,
                              void* d_out, int out_size)
{
    const float* x  = (const float*)d_in[0];
    const float* Wq = (const float*)d_in[1];
    const float* Wk = (const float*)d_in[2];
    const float* Wv = (const float*)d_in[3];
    float* out = (float*)d_out;

    cudaFuncSetAttribute(qkv_kernel, cudaFuncAttributeMaxDynamicSharedMemorySize, SMEM_QKV);
    cudaFuncSetAttribute(qk_kernel,  cudaFuncAttributeMaxDynamicSharedMemorySize, SMEM_QKV);
    cudaFuncSetAttribute(pv_kernel,  cudaFuncAttributeMaxDynamicSharedMemorySize, SMEM_PV);

    conv_all_kernel<<<(XN4 + 3 * WN4 + 255) / 256, 256>>>(x, Wq, Wk, Wv);

    dim3 g_qkv(DIM / BN, (BATCH * SEQ) / BM, 3);        // (8, 64, 3)
    qkv_kernel<<<g_qkv, NTHREADS, SMEM_QKV>>>();

    dim3 g_qk(SEQ / BN, SEQ / BM, BATCH);               // (16, 16, 4)
    qk_kernel<<<g_qk, NTHREADS, SMEM_QKV>>>();

    softmax_kernel<<<BATCH * SEQ, 256>>>();

    dim3 g_pv(DIM / BN, SEQ / BM, BATCH);               // (8, 16, 4)
    pv_kernel<<<g_pv, NTHREADS, SMEM_PV>>>(out);
}